// round 6
// baseline (speedup 1.0000x reference)
#include <cuda_runtime.h>
#include <cuda_fp16.h>
#include <cstdint>

#define BATCH 16
#define HW    16384
#define C     64
#define CHUNKS 64            // 256 rows per CTA, 4 stages of 64

__device__ float g_partial[BATCH * CHUNKS * C * C];   // 16 MB scratch
__device__ float g_attn[BATCH * C * C];

// ---------------------------------------------------------------------------
// helpers
// ---------------------------------------------------------------------------
__device__ __forceinline__ uint32_t smem_u32(const void* p) {
    uint32_t a;
    asm("{ .reg .u64 t; cvta.to.shared.u64 t, %1; cvt.u32.u64 %0, t; }"
        : "=r"(a) : "l"(p));
    return a;
}
__device__ __forceinline__ uint32_t sw128(uint32_t o) {
    return o ^ ((o >> 3) & 0x70);
}
__device__ __forceinline__ uint32_t h2u(__half2 h) {
    return *reinterpret_cast<uint32_t*>(&h);
}

#define LDSM4T(r, a)                                                          \
    asm volatile("ldmatrix.sync.aligned.m8n8.x4.trans.shared.b16 "            \
                 "{%0,%1,%2,%3}, [%4];"                                       \
                 : "=r"((r)[0]), "=r"((r)[1]), "=r"((r)[2]), "=r"((r)[3])     \
                 : "r"(a))
#define LDSM4(r, a)                                                           \
    asm volatile("ldmatrix.sync.aligned.m8n8.x4.shared.b16 "                  \
                 "{%0,%1,%2,%3}, [%4];"                                       \
                 : "=r"((r)[0]), "=r"((r)[1]), "=r"((r)[2]), "=r"((r)[3])     \
                 : "r"(a))
#define MMA(d, a, b0, b1)                                                     \
    asm volatile("mma.sync.aligned.m16n8k16.row.col.f32.f16.f16.f32 "         \
                 "{%0,%1,%2,%3}, {%4,%5,%6,%7}, {%8,%9}, {%0,%1,%2,%3};"      \
                 : "+f"((d)[0]), "+f"((d)[1]), "+f"((d)[2]), "+f"((d)[3])     \
                 : "r"((a)[0]), "r"((a)[1]), "r"((a)[2]), "r"((a)[3]),        \
                   "r"(b0), "r"(b1))

// tile: 64 rows x 64 fp16 cols, 128B row stride, SW128 swizzle, 8KB
#define TILE 8192

// exact Dekker split of 4 floats into hi/lo fp16x2 pairs
__device__ __forceinline__ void split4(float4 x, uint32_t& h0, uint32_t& h1,
                                       uint32_t& l0, uint32_t& l1) {
    __half2 a01 = __floats2half2_rn(x.x, x.y);
    __half2 a23 = __floats2half2_rn(x.z, x.w);
    float2 f01 = __half22float2(a01);
    float2 f23 = __half22float2(a23);
    __half2 b01 = __floats2half2_rn(x.x - f01.x, x.y - f01.y);
    __half2 b23 = __floats2half2_rn(x.z - f23.x, x.w - f23.y);
    h0 = h2u(a01); h1 = h2u(a23); l0 = h2u(b01); l1 = h2u(b23);
}

// ---------------------------------------------------------------------------
// Kernel 1: partial scores. S[b][q][k] = sum_r Q[b][r][q]*K[b][r][k]
// A = Q^T (ldmatrix.trans), B = K (ldmatrix.trans).
// fp16 2-level exact split, 3 products (hh + hl + lh); l*l ~ 2^-22 omitted.
// ---------------------------------------------------------------------------
__global__ void __launch_bounds__(128, 5)
k1_scores(const float* __restrict__ Q, const float* __restrict__ K) {
    __shared__ __align__(1024) uint8_t sm[4 * TILE];   // Qh Ql Kh Kl
    uint32_t sb = smem_u32(sm);

    int t = threadIdx.x, lane = t & 31, w = t >> 5;
    int b = blockIdx.x >> 6;
    int chunk = blockIdx.x & 63;
    int qb = w * 16;

    const float* Qb = Q + ((size_t)b * HW + chunk * 256) * C;
    const float* Kb = K + ((size_t)b * HW + chunk * 256) * C;

    float d[8][4];
#pragma unroll
    for (int i = 0; i < 8; ++i)
#pragma unroll
        for (int j = 0; j < 4; ++j) d[i][j] = 0.f;

    const int li = lane & 7, mi = lane >> 3;
    const int rA = ((mi & 2) << 2) + li;
    const int cA = qb + ((mi & 1) << 3);
    const int rB = ((mi & 1) << 3) + li;
    const int cBo = (mi & 2) << 2;

    for (int s = 0; s < 4; ++s) {
        __syncthreads();   // prev-stage ldmatrix reads complete
#pragma unroll
        for (int it = 0; it < 8; ++it) {
            int idx = t + it * 128;               // 0..1023
            int r = idx >> 4, c4 = idx & 15;
            uint32_t off = sw128((uint32_t)(r * 128 + c4 * 8));
            uint32_t h0, h1, l0, l1;
            split4(*(const float4*)(Qb + (size_t)(s * 64 + r) * C + c4 * 4),
                   h0, h1, l0, l1);
            *(uint2*)(sm + 0 * TILE + off) = make_uint2(h0, h1);
            *(uint2*)(sm + 1 * TILE + off) = make_uint2(l0, l1);
            split4(*(const float4*)(Kb + (size_t)(s * 64 + r) * C + c4 * 4),
                   h0, h1, l0, l1);
            *(uint2*)(sm + 2 * TILE + off) = make_uint2(h0, h1);
            *(uint2*)(sm + 3 * TILE + off) = make_uint2(l0, l1);
        }
        __syncthreads();

#pragma unroll
        for (int kst = 0; kst < 4; ++kst) {
            int r0 = kst * 16;
            uint32_t Ah[4], Al[4];
            uint32_t aoff = sw128((uint32_t)((r0 + rA) * 128 + cA * 2));
            LDSM4T(Ah, sb + 0 * TILE + aoff);
            LDSM4T(Al, sb + 1 * TILE + aoff);
#pragma unroll
            for (int np = 0; np < 4; ++np) {
                uint32_t Bh[4], Bl[4];
                uint32_t boff =
                    sw128((uint32_t)((r0 + rB) * 128 + (np * 16 + cBo) * 2));
                LDSM4T(Bh, sb + 2 * TILE + boff);
                LDSM4T(Bl, sb + 3 * TILE + boff);
                float* d0 = d[2 * np];
                float* d1 = d[2 * np + 1];
                MMA(d0, Ah, Bh[0], Bh[1]); MMA(d1, Ah, Bh[2], Bh[3]);
                MMA(d0, Ah, Bl[0], Bl[1]); MMA(d1, Ah, Bl[2], Bl[3]);
                MMA(d0, Al, Bh[0], Bh[1]); MMA(d1, Al, Bh[2], Bh[3]);
            }
        }
    }

    float* pb = g_partial + ((size_t)b * CHUNKS + chunk) * (C * C);
    int mrow = qb + (lane >> 2);
    int mcol = 2 * (lane & 3);
#pragma unroll
    for (int nt = 0; nt < 8; ++nt) {
        *(float2*)(pb + mrow * C + nt * 8 + mcol) = make_float2(d[nt][0], d[nt][1]);
        *(float2*)(pb + (mrow + 8) * C + nt * 8 + mcol) = make_float2(d[nt][2], d[nt][3]);
    }
}

// ---------------------------------------------------------------------------
// Kernel 2: reduce 64 chunk partials + softmax over k.
// ---------------------------------------------------------------------------
__global__ __launch_bounds__(256) void k2_softmax() {
    __shared__ float S[256];
    int b = blockIdx.x >> 4;
    int qg = blockIdx.x & 15;
    int t = threadIdx.x;
    int q = qg * 4 + (t >> 6);
    int k = t & 63;

    const float* p = g_partial + (size_t)b * CHUNKS * (C * C) + q * C + k;
    float acc = 0.f;
#pragma unroll 8
    for (int ch = 0; ch < CHUNKS; ++ch) acc += p[(size_t)ch * (C * C)];
    S[t] = acc;
    __syncthreads();

    int w = t >> 5, lane = t & 31;
    if (w < 4) {
        float e0 = S[w * 64 + lane];
        float e1 = S[w * 64 + 32 + lane];
        float m = fmaxf(e0, e1);
#pragma unroll
        for (int o = 16; o > 0; o >>= 1) m = fmaxf(m, __shfl_xor_sync(~0u, m, o));
        float x0 = expf(e0 - m), x1 = expf(e1 - m);
        float s = x0 + x1;
#pragma unroll
        for (int o = 16; o > 0; o >>= 1) s += __shfl_xor_sync(~0u, s, o);
        float inv = 1.f / s;
        float* a = g_attn + (size_t)b * (C * C) + (qg * 4 + w) * C;
        a[lane] = x0 * inv;
        a[lane + 32] = x1 * inv;
    }
}

// ---------------------------------------------------------------------------
// Kernel 3: out[b][r][q] = sum_k attn[b][q][k] * V[b][r][k]
// A = V (non-trans ldmatrix), B = attn^T (trans ldmatrix, staged once).
// fp16 2-level split, 3 products.
// ---------------------------------------------------------------------------
__global__ void __launch_bounds__(128, 5)
k3_out(const float* __restrict__ V, float* __restrict__ O) {
    __shared__ __align__(1024) uint8_t sm[4 * TILE];   // Vh Vl Bh Bl
    uint32_t sb = smem_u32(sm);

    int t = threadIdx.x, lane = t & 31, w = t >> 5;
    int b = blockIdx.x >> 6;
    int rg = blockIdx.x & 63;
    size_t row0 = (size_t)b * HW + rg * 256;

    // stage attn^T once: sB[k][q], hi/lo fp16
    const float* ab = g_attn + (size_t)b * (C * C);
#pragma unroll
    for (int it = 0; it < 8; ++it) {
        int idx = t + it * 128;
        int q = idx >> 4, c4 = idx & 15;
        float4 x = *(const float4*)(ab + q * 64 + c4 * 4);
        float xs[4] = {x.x, x.y, x.z, x.w};
#pragma unroll
        for (int j = 0; j < 4; ++j) {
            int k = c4 * 4 + j;
            uint32_t off = sw128((uint32_t)(k * 128 + q * 2));
            __half h = __float2half_rn(xs[j]);
            __half l = __float2half_rn(xs[j] - __half2float(h));
            *(__half*)(sm + 2 * TILE + off) = h;
            *(__half*)(sm + 3 * TILE + off) = l;
        }
    }

    const int li = lane & 7, mi = lane >> 3;
    const int rVA = w * 16 + ((mi & 1) << 3) + li;
    const int cVAo = (mi & 2) << 2;
    const int rB = ((mi & 1) << 3) + li;
    const int cBo = (mi & 2) << 2;
    int mrow = w * 16 + (lane >> 2);
    int mcol = 2 * (lane & 3);

    for (int s = 0; s < 4; ++s) {
        __syncthreads();
#pragma unroll
        for (int it = 0; it < 8; ++it) {
            int idx = t + it * 128;
            int r = idx >> 4, c4 = idx & 15;
            uint32_t off = sw128((uint32_t)(r * 128 + c4 * 8));
            uint32_t h0, h1, l0, l1;
            split4(*(const float4*)(V + (row0 + s * 64 + r) * C + c4 * 4),
                   h0, h1, l0, l1);
            *(uint2*)(sm + 0 * TILE + off) = make_uint2(h0, h1);
            *(uint2*)(sm + 1 * TILE + off) = make_uint2(l0, l1);
        }
        __syncthreads();

        float d[8][4];
#pragma unroll
        for (int i = 0; i < 8; ++i)
#pragma unroll
            for (int j = 0; j < 4; ++j) d[i][j] = 0.f;

#pragma unroll
        for (int kst = 0; kst < 4; ++kst) {
            int k0 = kst * 16;
            uint32_t Ah[4], Al[4];
            uint32_t aoff = sw128((uint32_t)(rVA * 128 + (k0 + cVAo) * 2));
            LDSM4(Ah, sb + 0 * TILE + aoff);
            LDSM4(Al, sb + 1 * TILE + aoff);
#pragma unroll
            for (int np = 0; np < 4; ++np) {
                uint32_t Bh[4], Bl[4];
                uint32_t boff =
                    sw128((uint32_t)((k0 + rB) * 128 + (np * 16 + cBo) * 2));
                LDSM4T(Bh, sb + 2 * TILE + boff);
                LDSM4T(Bl, sb + 3 * TILE + boff);
                float* d0 = d[2 * np];
                float* d1 = d[2 * np + 1];
                MMA(d0, Ah, Bh[0], Bh[1]); MMA(d1, Ah, Bh[2], Bh[3]);
                MMA(d0, Ah, Bl[0], Bl[1]); MMA(d1, Ah, Bl[2], Bl[3]);
                MMA(d0, Al, Bh[0], Bh[1]); MMA(d1, Al, Bh[2], Bh[3]);
            }
        }

        float* Ob = O + (row0 + s * 64) * C;
#pragma unroll
        for (int nt = 0; nt < 8; ++nt) {
            *(float2*)(Ob + (size_t)mrow * C + nt * 8 + mcol) =
                make_float2(d[nt][0], d[nt][1]);
            *(float2*)(Ob + (size_t)(mrow + 8) * C + nt * 8 + mcol) =
                make_float2(d[nt][2], d[nt][3]);
        }
    }
}

// ---------------------------------------------------------------------------
extern "C" void kernel_launch(void* const* d_in, const int* in_sizes, int n_in,
                              void* d_out, int out_size) {
    const float* q = (const float*)d_in[0];
    const float* k = (const float*)d_in[1];
    const float* v = (const float*)d_in[2];
    float* out = (float*)d_out;

    k1_scores<<<BATCH * CHUNKS, 128>>>(q, k);
    k2_softmax<<<BATCH * 16, 256>>>();
    k3_out<<<BATCH * CHUNKS, 128>>>(v, out);
}

// round 7
// speedup vs baseline: 1.0436x; 1.0436x over previous
#include <cuda_runtime.h>
#include <cuda_fp16.h>
#include <cstdint>

#define BATCH 16
#define HW    16384
#define C     64
#define CHUNKS 32            // 512 rows per CTA, 8 stages of 64

__device__ float g_partial[BATCH * CHUNKS * C * C];   // 8 MB scratch
__device__ float g_attn[BATCH * C * C];

// ---------------------------------------------------------------------------
// helpers
// ---------------------------------------------------------------------------
__device__ __forceinline__ uint32_t smem_u32(const void* p) {
    uint32_t a;
    asm("{ .reg .u64 t; cvta.to.shared.u64 t, %1; cvt.u32.u64 %0, t; }"
        : "=r"(a) : "l"(p));
    return a;
}
__device__ __forceinline__ uint32_t sw128(uint32_t o) {
    return o ^ ((o >> 3) & 0x70);
}
__device__ __forceinline__ uint32_t h2u(__half2 h) {
    return *reinterpret_cast<uint32_t*>(&h);
}

#define LDSM4T(r, a)                                                          \
    asm volatile("ldmatrix.sync.aligned.m8n8.x4.trans.shared.b16 "            \
                 "{%0,%1,%2,%3}, [%4];"                                       \
                 : "=r"((r)[0]), "=r"((r)[1]), "=r"((r)[2]), "=r"((r)[3])     \
                 : "r"(a))
#define LDSM4(r, a)                                                           \
    asm volatile("ldmatrix.sync.aligned.m8n8.x4.shared.b16 "                  \
                 "{%0,%1,%2,%3}, [%4];"                                       \
                 : "=r"((r)[0]), "=r"((r)[1]), "=r"((r)[2]), "=r"((r)[3])     \
                 : "r"(a))
#define MMA(d, a, b0, b1)                                                     \
    asm volatile("mma.sync.aligned.m16n8k16.row.col.f32.f16.f16.f32 "         \
                 "{%0,%1,%2,%3}, {%4,%5,%6,%7}, {%8,%9}, {%0,%1,%2,%3};"      \
                 : "+f"((d)[0]), "+f"((d)[1]), "+f"((d)[2]), "+f"((d)[3])     \
                 : "r"((a)[0]), "r"((a)[1]), "r"((a)[2]), "r"((a)[3]),        \
                   "r"(b0), "r"(b1))

// tile: 64 rows x 64 fp16 cols, 128B row stride, SW128 swizzle, 8KB
#define TILE 8192

// exact Dekker split of 4 floats into hi/lo fp16x2 pairs
__device__ __forceinline__ void split4(float4 x, uint32_t& h0, uint32_t& h1,
                                       uint32_t& l0, uint32_t& l1) {
    __half2 a01 = __floats2half2_rn(x.x, x.y);
    __half2 a23 = __floats2half2_rn(x.z, x.w);
    float2 f01 = __half22float2(a01);
    float2 f23 = __half22float2(a23);
    __half2 b01 = __floats2half2_rn(x.x - f01.x, x.y - f01.y);
    __half2 b23 = __floats2half2_rn(x.z - f23.x, x.w - f23.y);
    h0 = h2u(a01); h1 = h2u(a23); l0 = h2u(b01); l1 = h2u(b23);
}

// ---------------------------------------------------------------------------
// Kernel 1: partial scores. S[b][q][k] = sum_r Q[b][r][q]*K[b][r][k]
// 256 threads, 8 warps; warp w: q-rows (w&3)*16..+15, n-cols ((w>>2)*2)*16..+31.
// fp16 2-level exact split, 3 products (hh + hl + lh).
// ---------------------------------------------------------------------------
__global__ void __launch_bounds__(256, 3)
k1_scores(const float* __restrict__ Q, const float* __restrict__ K) {
    __shared__ __align__(1024) uint8_t sm[4 * TILE];   // Qh Ql Kh Kl
    uint32_t sb = smem_u32(sm);

    int t = threadIdx.x, lane = t & 31, w = t >> 5;
    int b = blockIdx.x >> 5;
    int chunk = blockIdx.x & 31;
    int qb = (w & 3) * 16;
    int nbase = (w >> 2) * 2;          // np = nbase, nbase+1

    const float* Qb = Q + ((size_t)b * HW + chunk * 512) * C;
    const float* Kb = K + ((size_t)b * HW + chunk * 512) * C;

    float d[4][4];
#pragma unroll
    for (int i = 0; i < 4; ++i)
#pragma unroll
        for (int j = 0; j < 4; ++j) d[i][j] = 0.f;

    const int li = lane & 7, mi = lane >> 3;
    const int rA = ((mi & 2) << 2) + li;
    const int cA = qb + ((mi & 1) << 3);
    const int rB = ((mi & 1) << 3) + li;
    const int cBo = (mi & 2) << 2;

    for (int s = 0; s < 8; ++s) {
        __syncthreads();   // prev-stage ldmatrix reads complete
#pragma unroll
        for (int it = 0; it < 4; ++it) {
            int idx = t + it * 256;               // 0..1023
            int r = idx >> 4, c4 = idx & 15;
            uint32_t off = sw128((uint32_t)(r * 128 + c4 * 8));
            uint32_t h0, h1, l0, l1;
            split4(*(const float4*)(Qb + (size_t)(s * 64 + r) * C + c4 * 4),
                   h0, h1, l0, l1);
            *(uint2*)(sm + 0 * TILE + off) = make_uint2(h0, h1);
            *(uint2*)(sm + 1 * TILE + off) = make_uint2(l0, l1);
            split4(*(const float4*)(Kb + (size_t)(s * 64 + r) * C + c4 * 4),
                   h0, h1, l0, l1);
            *(uint2*)(sm + 2 * TILE + off) = make_uint2(h0, h1);
            *(uint2*)(sm + 3 * TILE + off) = make_uint2(l0, l1);
        }
        __syncthreads();

#pragma unroll
        for (int kst = 0; kst < 4; ++kst) {
            int r0 = kst * 16;
            uint32_t Ah[4], Al[4];
            uint32_t aoff = sw128((uint32_t)((r0 + rA) * 128 + cA * 2));
            LDSM4T(Ah, sb + 0 * TILE + aoff);
            LDSM4T(Al, sb + 1 * TILE + aoff);
#pragma unroll
            for (int j = 0; j < 2; ++j) {
                int np = nbase + j;
                uint32_t Bh[4], Bl[4];
                uint32_t boff =
                    sw128((uint32_t)((r0 + rB) * 128 + (np * 16 + cBo) * 2));
                LDSM4T(Bh, sb + 2 * TILE + boff);
                LDSM4T(Bl, sb + 3 * TILE + boff);
                float* d0 = d[2 * j];
                float* d1 = d[2 * j + 1];
                MMA(d0, Ah, Bh[0], Bh[1]); MMA(d1, Ah, Bh[2], Bh[3]);
                MMA(d0, Ah, Bl[0], Bl[1]); MMA(d1, Ah, Bl[2], Bl[3]);
                MMA(d0, Al, Bh[0], Bh[1]); MMA(d1, Al, Bh[2], Bh[3]);
            }
        }
    }

    float* pb = g_partial + ((size_t)b * CHUNKS + chunk) * (C * C);
    int mrow = qb + (lane >> 2);
    int mcol = 2 * (lane & 3);
#pragma unroll
    for (int j = 0; j < 2; ++j) {
        int np = nbase + j;
        *(float2*)(pb + mrow * C + np * 16 + mcol) =
            make_float2(d[2 * j][0], d[2 * j][1]);
        *(float2*)(pb + (mrow + 8) * C + np * 16 + mcol) =
            make_float2(d[2 * j][2], d[2 * j][3]);
        *(float2*)(pb + mrow * C + np * 16 + 8 + mcol) =
            make_float2(d[2 * j + 1][0], d[2 * j + 1][1]);
        *(float2*)(pb + (mrow + 8) * C + np * 16 + 8 + mcol) =
            make_float2(d[2 * j + 1][2], d[2 * j + 1][3]);
    }
}

// ---------------------------------------------------------------------------
// Kernel 2: reduce 32 chunk partials + softmax over k.
// ---------------------------------------------------------------------------
__global__ __launch_bounds__(256) void k2_softmax() {
    __shared__ float S[256];
    int b = blockIdx.x >> 4;
    int qg = blockIdx.x & 15;
    int t = threadIdx.x;
    int q = qg * 4 + (t >> 6);
    int k = t & 63;

    const float* p = g_partial + (size_t)b * CHUNKS * (C * C) + q * C + k;
    float acc = 0.f;
#pragma unroll 8
    for (int ch = 0; ch < CHUNKS; ++ch) acc += p[(size_t)ch * (C * C)];
    S[t] = acc;
    __syncthreads();

    int w = t >> 5, lane = t & 31;
    if (w < 4) {
        float e0 = S[w * 64 + lane];
        float e1 = S[w * 64 + 32 + lane];
        float m = fmaxf(e0, e1);
#pragma unroll
        for (int o = 16; o > 0; o >>= 1) m = fmaxf(m, __shfl_xor_sync(~0u, m, o));
        float x0 = expf(e0 - m), x1 = expf(e1 - m);
        float s = x0 + x1;
#pragma unroll
        for (int o = 16; o > 0; o >>= 1) s += __shfl_xor_sync(~0u, s, o);
        float inv = 1.f / s;
        float* a = g_attn + (size_t)b * (C * C) + (qg * 4 + w) * C;
        a[lane] = x0 * inv;
        a[lane + 32] = x1 * inv;
    }
}

// ---------------------------------------------------------------------------
// Kernel 3: out[b][r][q] = sum_k attn[b][q][k] * V[b][r][k]
// A = V (non-trans ldmatrix). B = attn[q][k] row-major == [n][k] storage ->
// NON-trans ldmatrix gives the b-fragment directly (no transpose staging).
// 256 threads; warp w: rows (w&3)*16, cols ((w>>2)*2)*16..+31.
// ---------------------------------------------------------------------------
__global__ void __launch_bounds__(256, 3)
k3_out(const float* __restrict__ V, float* __restrict__ O) {
    __shared__ __align__(1024) uint8_t sm[4 * TILE];   // Vh Vl Bh Bl
    uint32_t sb = smem_u32(sm);

    int t = threadIdx.x, lane = t & 31, w = t >> 5;
    int b = blockIdx.x >> 5;
    int rg = blockIdx.x & 31;
    size_t row0 = (size_t)b * HW + rg * 512;
    int rowg = (w & 3) * 16;
    int nbase = (w >> 2) * 2;

    // stage attn once: B tile [q][k] hi/lo fp16, coalesced split4 path
    const float* ab = g_attn + (size_t)b * (C * C);
#pragma unroll
    for (int it = 0; it < 4; ++it) {
        int idx = t + it * 256;
        int q = idx >> 4, c4 = idx & 15;
        uint32_t off = sw128((uint32_t)(q * 128 + c4 * 8));
        uint32_t h0, h1, l0, l1;
        split4(*(const float4*)(ab + q * 64 + c4 * 4), h0, h1, l0, l1);
        *(uint2*)(sm + 2 * TILE + off) = make_uint2(h0, h1);
        *(uint2*)(sm + 3 * TILE + off) = make_uint2(l0, l1);
    }

    const int li = lane & 7, mi = lane >> 3;
    const int rVA = rowg + ((mi & 1) << 3) + li;     // V rows
    const int cVAo = (mi & 2) << 2;                  // k + 8
    const int rBq = ((mi & 1) << 3) + li;            // B rows = q
    const int cBo = (mi & 2) << 2;                   // k + 8
    int mrow = rowg + (lane >> 2);
    int mcol = 2 * (lane & 3);

    for (int s = 0; s < 8; ++s) {
        __syncthreads();   // B ready (s=0) / V reuse safe (s>0)
#pragma unroll
        for (int it = 0; it < 4; ++it) {
            int idx = t + it * 256;
            int r = idx >> 4, c4 = idx & 15;
            uint32_t off = sw128((uint32_t)(r * 128 + c4 * 8));
            uint32_t h0, h1, l0, l1;
            split4(*(const float4*)(V + (row0 + s * 64 + r) * C + c4 * 4),
                   h0, h1, l0, l1);
            *(uint2*)(sm + 0 * TILE + off) = make_uint2(h0, h1);
            *(uint2*)(sm + 1 * TILE + off) = make_uint2(l0, l1);
        }
        __syncthreads();

        float d[4][4];
#pragma unroll
        for (int i = 0; i < 4; ++i)
#pragma unroll
            for (int j = 0; j < 4; ++j) d[i][j] = 0.f;

#pragma unroll
        for (int kst = 0; kst < 4; ++kst) {
            int k0 = kst * 16;
            uint32_t Ah[4], Al[4];
            uint32_t aoff = sw128((uint32_t)(rVA * 128 + (k0 + cVAo) * 2));
            LDSM4(Ah, sb + 0 * TILE + aoff);
            LDSM4(Al, sb + 1 * TILE + aoff);
#pragma unroll
            for (int j = 0; j < 2; ++j) {
                int np = nbase + j;
                uint32_t Bh[4], Bl[4];
                uint32_t boff =
                    sw128((uint32_t)((np * 16 + rBq) * 128 + (k0 + cBo) * 2));
                LDSM4(Bh, sb + 2 * TILE + boff);     // non-trans: rows = q
                LDSM4(Bl, sb + 3 * TILE + boff);
                float* d0 = d[2 * j];
                float* d1 = d[2 * j + 1];
                // mat0: q0-7/k0-7, mat1: q8-15/k0-7, mat2: q0-7/k8-15, mat3: q8-15/k8-15
                MMA(d0, Ah, Bh[0], Bh[2]); MMA(d1, Ah, Bh[1], Bh[3]);
                MMA(d0, Ah, Bl[0], Bl[2]); MMA(d1, Ah, Bl[1], Bl[3]);
                MMA(d0, Al, Bh[0], Bh[2]); MMA(d1, Al, Bh[1], Bh[3]);
            }
        }

        float* Ob = O + (row0 + s * 64) * C;
#pragma unroll
        for (int j = 0; j < 2; ++j) {
            int np = nbase + j;
            *(float2*)(Ob + (size_t)mrow * C + np * 16 + mcol) =
                make_float2(d[2 * j][0], d[2 * j][1]);
            *(float2*)(Ob + (size_t)(mrow + 8) * C + np * 16 + mcol) =
                make_float2(d[2 * j][2], d[2 * j][3]);
            *(float2*)(Ob + (size_t)mrow * C + np * 16 + 8 + mcol) =
                make_float2(d[2 * j + 1][0], d[2 * j + 1][1]);
            *(float2*)(Ob + (size_t)(mrow + 8) * C + np * 16 + 8 + mcol) =
                make_float2(d[2 * j + 1][2], d[2 * j + 1][3]);
        }
    }
}

// ---------------------------------------------------------------------------
extern "C" void kernel_launch(void* const* d_in, const int* in_sizes, int n_in,
                              void* d_out, int out_size) {
    const float* q = (const float*)d_in[0];
    const float* k = (const float*)d_in[1];
    const float* v = (const float*)d_in[2];
    float* out = (float*)d_out;

    k1_scores<<<BATCH * CHUNKS, 256>>>(q, k);
    k2_softmax<<<BATCH * 16, 256>>>();
    k3_out<<<BATCH * CHUNKS, 256>>>(v, out);
}

// round 8
// speedup vs baseline: 1.2783x; 1.2248x over previous
#include <cuda_runtime.h>
#include <cuda_fp16.h>
#include <cstdint>

#define BATCH 16
#define HW    16384
#define C     64
#define CHUNKS 32            // 512 rows per CTA, 8 stages of 64

__device__ float g_partial[BATCH * CHUNKS * C * C];   // 8 MB scratch
__device__ float g_attn[BATCH * C * C];

// ---------------------------------------------------------------------------
// helpers
// ---------------------------------------------------------------------------
__device__ __forceinline__ uint32_t smem_u32(const void* p) {
    uint32_t a;
    asm("{ .reg .u64 t; cvta.to.shared.u64 t, %1; cvt.u32.u64 %0, t; }"
        : "=r"(a) : "l"(p));
    return a;
}
__device__ __forceinline__ uint32_t sw128(uint32_t o) {
    return o ^ ((o >> 3) & 0x70);
}
__device__ __forceinline__ uint32_t h2u(__half2 h) {
    return *reinterpret_cast<uint32_t*>(&h);
}

#define LDSM4T(r, a)                                                          \
    asm volatile("ldmatrix.sync.aligned.m8n8.x4.trans.shared.b16 "            \
                 "{%0,%1,%2,%3}, [%4];"                                       \
                 : "=r"((r)[0]), "=r"((r)[1]), "=r"((r)[2]), "=r"((r)[3])     \
                 : "r"(a))
#define LDSM4(r, a)                                                           \
    asm volatile("ldmatrix.sync.aligned.m8n8.x4.shared.b16 "                  \
                 "{%0,%1,%2,%3}, [%4];"                                       \
                 : "=r"((r)[0]), "=r"((r)[1]), "=r"((r)[2]), "=r"((r)[3])     \
                 : "r"(a))
#define MMA(d, a, b0, b1)                                                     \
    asm volatile("mma.sync.aligned.m16n8k16.row.col.f32.f16.f16.f32 "         \
                 "{%0,%1,%2,%3}, {%4,%5,%6,%7}, {%8,%9}, {%0,%1,%2,%3};"      \
                 : "+f"((d)[0]), "+f"((d)[1]), "+f"((d)[2]), "+f"((d)[3])     \
                 : "r"((a)[0]), "r"((a)[1]), "r"((a)[2]), "r"((a)[3]),        \
                   "r"(b0), "r"(b1))

// tile: 64 rows x 64 fp16 cols, 128B row stride, SW128 swizzle, 8KB
#define TILE 8192

// exact Dekker split of 4 floats into hi/lo fp16x2 pairs
__device__ __forceinline__ void split4(float4 x, uint32_t& h0, uint32_t& h1,
                                       uint32_t& l0, uint32_t& l1) {
    __half2 a01 = __floats2half2_rn(x.x, x.y);
    __half2 a23 = __floats2half2_rn(x.z, x.w);
    float2 f01 = __half22float2(a01);
    float2 f23 = __half22float2(a23);
    __half2 b01 = __floats2half2_rn(x.x - f01.x, x.y - f01.y);
    __half2 b23 = __floats2half2_rn(x.z - f23.x, x.w - f23.y);
    h0 = h2u(a01); h1 = h2u(a23); l0 = h2u(b01); l1 = h2u(b23);
}

// ---------------------------------------------------------------------------
// Kernel 1: partial scores. S[b][q][k] = sum_r Q[b][r][q]*K[b][r][k]
// 256 threads, 8 warps; warp w: q-rows (w&3)*16..+15, n-cols ((w>>2)*2)*16..+31.
// fp16 2-level exact split, 3 products. 2-deep register-prefetch pipeline:
// LDG for stage s+1 issues before the MMA phase of stage s.
// ---------------------------------------------------------------------------
__global__ void __launch_bounds__(256, 2)
k1_scores(const float* __restrict__ Q, const float* __restrict__ K) {
    __shared__ __align__(1024) uint8_t sm[4 * TILE];   // Qh Ql Kh Kl
    uint32_t sb = smem_u32(sm);

    int t = threadIdx.x, lane = t & 31, w = t >> 5;
    int b = blockIdx.x >> 5;
    int chunk = blockIdx.x & 31;
    int qb = (w & 3) * 16;
    int nbase = (w >> 2) * 2;

    const float* Qb = Q + ((size_t)b * HW + chunk * 512) * C;
    const float* Kb = K + ((size_t)b * HW + chunk * 512) * C;

    // this thread's 4 staging slots (row r, float4-col c4), constant across stages
    int rr[4], cc[4];
#pragma unroll
    for (int it = 0; it < 4; ++it) {
        int idx = t + it * 256;
        rr[it] = idx >> 4;
        cc[it] = (idx & 15) * 4;
    }

    float d[4][4];
#pragma unroll
    for (int i = 0; i < 4; ++i)
#pragma unroll
        for (int j = 0; j < 4; ++j) d[i][j] = 0.f;

    const int li = lane & 7, mi = lane >> 3;
    const int rA = ((mi & 2) << 2) + li;
    const int cA = qb + ((mi & 1) << 3);
    const int rB = ((mi & 1) << 3) + li;
    const int cBo = (mi & 2) << 2;

    // prefetch stage 0
    float4 pq[4], pk[4];
#pragma unroll
    for (int it = 0; it < 4; ++it) {
        pq[it] = *(const float4*)(Qb + (size_t)rr[it] * C + cc[it]);
        pk[it] = *(const float4*)(Kb + (size_t)rr[it] * C + cc[it]);
    }

    for (int s = 0; s < 8; ++s) {
        // convert + STS from prefetched registers
#pragma unroll
        for (int it = 0; it < 4; ++it) {
            uint32_t off = sw128((uint32_t)(rr[it] * 128 + cc[it] * 2));
            uint32_t h0, h1, l0, l1;
            split4(pq[it], h0, h1, l0, l1);
            *(uint2*)(sm + 0 * TILE + off) = make_uint2(h0, h1);
            *(uint2*)(sm + 1 * TILE + off) = make_uint2(l0, l1);
            split4(pk[it], h0, h1, l0, l1);
            *(uint2*)(sm + 2 * TILE + off) = make_uint2(h0, h1);
            *(uint2*)(sm + 3 * TILE + off) = make_uint2(l0, l1);
        }
        __syncthreads();   // tiles ready

        // issue next stage's loads now; consumed next iteration (overlaps MMA)
        if (s < 7) {
            const float* Qn = Qb + (size_t)(s + 1) * 64 * C;
            const float* Kn = Kb + (size_t)(s + 1) * 64 * C;
#pragma unroll
            for (int it = 0; it < 4; ++it) {
                pq[it] = *(const float4*)(Qn + (size_t)rr[it] * C + cc[it]);
                pk[it] = *(const float4*)(Kn + (size_t)rr[it] * C + cc[it]);
            }
        }

#pragma unroll
        for (int kst = 0; kst < 4; ++kst) {
            int r0 = kst * 16;
            uint32_t Ah[4], Al[4];
            uint32_t aoff = sw128((uint32_t)((r0 + rA) * 128 + cA * 2));
            LDSM4T(Ah, sb + 0 * TILE + aoff);
            LDSM4T(Al, sb + 1 * TILE + aoff);
#pragma unroll
            for (int j = 0; j < 2; ++j) {
                int np = nbase + j;
                uint32_t Bh[4], Bl[4];
                uint32_t boff =
                    sw128((uint32_t)((r0 + rB) * 128 + (np * 16 + cBo) * 2));
                LDSM4T(Bh, sb + 2 * TILE + boff);
                LDSM4T(Bl, sb + 3 * TILE + boff);
                float* d0 = d[2 * j];
                float* d1 = d[2 * j + 1];
                MMA(d0, Ah, Bh[0], Bh[1]); MMA(d1, Ah, Bh[2], Bh[3]);
                MMA(d0, Ah, Bl[0], Bl[1]); MMA(d1, Ah, Bl[2], Bl[3]);
                MMA(d0, Al, Bh[0], Bh[1]); MMA(d1, Al, Bh[2], Bh[3]);
            }
        }
        __syncthreads();   // MMA reads done before next STS overwrites
    }

    float* pb = g_partial + ((size_t)b * CHUNKS + chunk) * (C * C);
    int mrow = qb + (lane >> 2);
    int mcol = 2 * (lane & 3);
#pragma unroll
    for (int j = 0; j < 2; ++j) {
        int np = nbase + j;
        *(float2*)(pb + mrow * C + np * 16 + mcol) =
            make_float2(d[2 * j][0], d[2 * j][1]);
        *(float2*)(pb + (mrow + 8) * C + np * 16 + mcol) =
            make_float2(d[2 * j][2], d[2 * j][3]);
        *(float2*)(pb + mrow * C + np * 16 + 8 + mcol) =
            make_float2(d[2 * j + 1][0], d[2 * j + 1][1]);
        *(float2*)(pb + (mrow + 8) * C + np * 16 + 8 + mcol) =
            make_float2(d[2 * j + 1][2], d[2 * j + 1][3]);
    }
}

// ---------------------------------------------------------------------------
// Kernel 2: reduce 32 chunk partials + softmax over k.
// ---------------------------------------------------------------------------
__global__ __launch_bounds__(256) void k2_softmax() {
    __shared__ float S[256];
    int b = blockIdx.x >> 4;
    int qg = blockIdx.x & 15;
    int t = threadIdx.x;
    int q = qg * 4 + (t >> 6);
    int k = t & 63;

    const float* p = g_partial + (size_t)b * CHUNKS * (C * C) + q * C + k;
    float acc = 0.f;
#pragma unroll 8
    for (int ch = 0; ch < CHUNKS; ++ch) acc += p[(size_t)ch * (C * C)];
    S[t] = acc;
    __syncthreads();

    int w = t >> 5, lane = t & 31;
    if (w < 4) {
        float e0 = S[w * 64 + lane];
        float e1 = S[w * 64 + 32 + lane];
        float m = fmaxf(e0, e1);
#pragma unroll
        for (int o = 16; o > 0; o >>= 1) m = fmaxf(m, __shfl_xor_sync(~0u, m, o));
        float x0 = expf(e0 - m), x1 = expf(e1 - m);
        float s = x0 + x1;
#pragma unroll
        for (int o = 16; o > 0; o >>= 1) s += __shfl_xor_sync(~0u, s, o);
        float inv = 1.f / s;
        float* a = g_attn + (size_t)b * (C * C) + (qg * 4 + w) * C;
        a[lane] = x0 * inv;
        a[lane + 32] = x1 * inv;
    }
}

// ---------------------------------------------------------------------------
// Kernel 3: out[b][r][q] = sum_k attn[b][q][k] * V[b][r][k]
// A = V (non-trans), B = attn (non-trans, staged once). Register prefetch of V.
// ---------------------------------------------------------------------------
__global__ void __launch_bounds__(256, 2)
k3_out(const float* __restrict__ V, float* __restrict__ O) {
    __shared__ __align__(1024) uint8_t sm[4 * TILE];   // Vh Vl Bh Bl
    uint32_t sb = smem_u32(sm);

    int t = threadIdx.x, lane = t & 31, w = t >> 5;
    int b = blockIdx.x >> 5;
    int rg = blockIdx.x & 31;
    size_t row0 = (size_t)b * HW + rg * 512;
    int rowg = (w & 3) * 16;
    int nbase = (w >> 2) * 2;

    int rr[4], cc[4];
#pragma unroll
    for (int it = 0; it < 4; ++it) {
        int idx = t + it * 256;
        rr[it] = idx >> 4;
        cc[it] = (idx & 15) * 4;
    }

    // stage attn once: B tile [q][k] hi/lo fp16
    const float* ab = g_attn + (size_t)b * (C * C);
#pragma unroll
    for (int it = 0; it < 4; ++it) {
        uint32_t off = sw128((uint32_t)(rr[it] * 128 + cc[it] * 2));
        uint32_t h0, h1, l0, l1;
        split4(*(const float4*)(ab + rr[it] * 64 + cc[it]), h0, h1, l0, l1);
        *(uint2*)(sm + 2 * TILE + off) = make_uint2(h0, h1);
        *(uint2*)(sm + 3 * TILE + off) = make_uint2(l0, l1);
    }

    const int li = lane & 7, mi = lane >> 3;
    const int rVA = rowg + ((mi & 1) << 3) + li;
    const int cVAo = (mi & 2) << 2;
    const int rBq = ((mi & 1) << 3) + li;
    const int cBo = (mi & 2) << 2;
    int mrow = rowg + (lane >> 2);
    int mcol = 2 * (lane & 3);

    // prefetch stage 0 of V
    float4 pv[4];
#pragma unroll
    for (int it = 0; it < 4; ++it)
        pv[it] = *(const float4*)(V + (row0 + rr[it]) * C + cc[it]);

    for (int s = 0; s < 8; ++s) {
        if (s) __syncthreads();   // V reuse safe (also covers B for s=0 via below)
#pragma unroll
        for (int it = 0; it < 4; ++it) {
            uint32_t off = sw128((uint32_t)(rr[it] * 128 + cc[it] * 2));
            uint32_t h0, h1, l0, l1;
            split4(pv[it], h0, h1, l0, l1);
            *(uint2*)(sm + 0 * TILE + off) = make_uint2(h0, h1);
            *(uint2*)(sm + 1 * TILE + off) = make_uint2(l0, l1);
        }
        __syncthreads();

        if (s < 7) {
            const float* Vn = V + (row0 + (size_t)(s + 1) * 64) * C;
#pragma unroll
            for (int it = 0; it < 4; ++it)
                pv[it] = *(const float4*)(Vn + (size_t)rr[it] * C + cc[it]);
        }

        float d[4][4];
#pragma unroll
        for (int i = 0; i < 4; ++i)
#pragma unroll
            for (int j = 0; j < 4; ++j) d[i][j] = 0.f;

#pragma unroll
        for (int kst = 0; kst < 4; ++kst) {
            int k0 = kst * 16;
            uint32_t Ah[4], Al[4];
            uint32_t aoff = sw128((uint32_t)(rVA * 128 + (k0 + cVAo) * 2));
            LDSM4(Ah, sb + 0 * TILE + aoff);
            LDSM4(Al, sb + 1 * TILE + aoff);
#pragma unroll
            for (int j = 0; j < 2; ++j) {
                int np = nbase + j;
                uint32_t Bh[4], Bl[4];
                uint32_t boff =
                    sw128((uint32_t)((np * 16 + rBq) * 128 + (k0 + cBo) * 2));
                LDSM4(Bh, sb + 2 * TILE + boff);
                LDSM4(Bl, sb + 3 * TILE + boff);
                float* d0 = d[2 * j];
                float* d1 = d[2 * j + 1];
                MMA(d0, Ah, Bh[0], Bh[2]); MMA(d1, Ah, Bh[1], Bh[3]);
                MMA(d0, Ah, Bl[0], Bl[2]); MMA(d1, Ah, Bl[1], Bl[3]);
                MMA(d0, Al, Bh[0], Bh[2]); MMA(d1, Al, Bh[1], Bh[3]);
            }
        }

        float* Ob = O + (row0 + s * 64) * C;
#pragma unroll
        for (int j = 0; j < 2; ++j) {
            int np = nbase + j;
            *(float2*)(Ob + (size_t)mrow * C + np * 16 + mcol) =
                make_float2(d[2 * j][0], d[2 * j][1]);
            *(float2*)(Ob + (size_t)(mrow + 8) * C + np * 16 + mcol) =
                make_float2(d[2 * j][2], d[2 * j][3]);
            *(float2*)(Ob + (size_t)mrow * C + np * 16 + 8 + mcol) =
                make_float2(d[2 * j + 1][0], d[2 * j + 1][1]);
            *(float2*)(Ob + (size_t)(mrow + 8) * C + np * 16 + 8 + mcol) =
                make_float2(d[2 * j + 1][2], d[2 * j + 1][3]);
        }
    }
}

// ---------------------------------------------------------------------------
extern "C" void kernel_launch(void* const* d_in, const int* in_sizes, int n_in,
                              void* d_out, int out_size) {
    const float* q = (const float*)d_in[0];
    const float* k = (const float*)d_in[1];
    const float* v = (const float*)d_in[2];
    float* out = (float*)d_out;

    k1_scores<<<BATCH * CHUNKS, 256>>>(q, k);
    k2_softmax<<<BATCH * 16, 256>>>();
    k3_out<<<BATCH * CHUNKS, 256>>>(v, out);
}

// round 9
// speedup vs baseline: 1.2828x; 1.0035x over previous
#include <cuda_runtime.h>
#include <cuda_fp16.h>
#include <cstdint>

#define BATCH 16
#define HW    16384
#define C     64
#define CHUNKS 32            // 512 rows per CTA, 8 stages of 64

__device__ float g_partial[BATCH * CHUNKS * C * C];   // 8 MB scratch
__device__ float g_attn[BATCH * C * C];

// ---------------------------------------------------------------------------
// helpers
// ---------------------------------------------------------------------------
__device__ __forceinline__ uint32_t smem_u32(const void* p) {
    uint32_t a;
    asm("{ .reg .u64 t; cvta.to.shared.u64 t, %1; cvt.u32.u64 %0, t; }"
        : "=r"(a) : "l"(p));
    return a;
}
__device__ __forceinline__ uint32_t sw128(uint32_t o) {
    return o ^ ((o >> 3) & 0x70);
}
__device__ __forceinline__ uint32_t h2u(__half2 h) {
    return *reinterpret_cast<uint32_t*>(&h);
}

#define LDSM4T(r, a)                                                          \
    asm volatile("ldmatrix.sync.aligned.m8n8.x4.trans.shared.b16 "            \
                 "{%0,%1,%2,%3}, [%4];"                                       \
                 : "=r"((r)[0]), "=r"((r)[1]), "=r"((r)[2]), "=r"((r)[3])     \
                 : "r"(a))
#define LDSM4(r, a)                                                           \
    asm volatile("ldmatrix.sync.aligned.m8n8.x4.shared.b16 "                  \
                 "{%0,%1,%2,%3}, [%4];"                                       \
                 : "=r"((r)[0]), "=r"((r)[1]), "=r"((r)[2]), "=r"((r)[3])     \
                 : "r"(a))
#define MMA(d, a, b0, b1)                                                     \
    asm volatile("mma.sync.aligned.m16n8k16.row.col.f32.f16.f16.f32 "         \
                 "{%0,%1,%2,%3}, {%4,%5,%6,%7}, {%8,%9}, {%0,%1,%2,%3};"      \
                 : "+f"((d)[0]), "+f"((d)[1]), "+f"((d)[2]), "+f"((d)[3])     \
                 : "r"((a)[0]), "r"((a)[1]), "r"((a)[2]), "r"((a)[3]),        \
                   "r"(b0), "r"(b1))

// tile: 64 rows x 64 fp16 cols, 128B row stride, SW128 swizzle, 8KB
#define TILE 8192

// exact Dekker split of 4 floats into hi/lo fp16x2 pairs
__device__ __forceinline__ void split4(float4 x, uint32_t& h0, uint32_t& h1,
                                       uint32_t& l0, uint32_t& l1) {
    __half2 a01 = __floats2half2_rn(x.x, x.y);
    __half2 a23 = __floats2half2_rn(x.z, x.w);
    float2 f01 = __half22float2(a01);
    float2 f23 = __half22float2(a23);
    __half2 b01 = __floats2half2_rn(x.x - f01.x, x.y - f01.y);
    __half2 b23 = __floats2half2_rn(x.z - f23.x, x.w - f23.y);
    h0 = h2u(a01); h1 = h2u(a23); l0 = h2u(b01); l1 = h2u(b23);
}

// ---------------------------------------------------------------------------
// Kernel 1: partial scores. S[b][q][k] = sum_r Q[b][r][q]*K[b][r][k]
// Register prefetch + DOUBLE-BUFFERED fp16 tiles -> one barrier per stage:
// MMA(s,buf) overlaps LDG/convert/STS(s+1,buf^1) across warps.
// ---------------------------------------------------------------------------
__global__ void __launch_bounds__(256, 2)
k1_scores(const float* __restrict__ Q, const float* __restrict__ K) {
    __shared__ __align__(1024) uint8_t sm[8 * TILE];   // [buf][Qh Ql Kh Kl]
    uint32_t sb = smem_u32(sm);

    int t = threadIdx.x, lane = t & 31, w = t >> 5;
    int b = blockIdx.x >> 5;
    int chunk = blockIdx.x & 31;
    int qb = (w & 3) * 16;
    int nbase = (w >> 2) * 2;

    const float* Qb = Q + ((size_t)b * HW + chunk * 512) * C;
    const float* Kb = K + ((size_t)b * HW + chunk * 512) * C;

    int rr[4], cc[4];
#pragma unroll
    for (int it = 0; it < 4; ++it) {
        int idx = t + it * 256;
        rr[it] = idx >> 4;
        cc[it] = (idx & 15) * 4;
    }

    float d[4][4];
#pragma unroll
    for (int i = 0; i < 4; ++i)
#pragma unroll
        for (int j = 0; j < 4; ++j) d[i][j] = 0.f;

    const int li = lane & 7, mi = lane >> 3;
    const int rA = ((mi & 2) << 2) + li;
    const int cA = qb + ((mi & 1) << 3);
    const int rB = ((mi & 1) << 3) + li;
    const int cBo = (mi & 2) << 2;

    float4 pq[4], pk[4];
#pragma unroll
    for (int it = 0; it < 4; ++it) {
        pq[it] = *(const float4*)(Qb + (size_t)rr[it] * C + cc[it]);
        pk[it] = *(const float4*)(Kb + (size_t)rr[it] * C + cc[it]);
    }

    for (int s = 0; s < 8; ++s) {
        uint32_t base = (uint32_t)((s & 1) * 4 * TILE);
        // convert + STS from prefetched registers into buf
#pragma unroll
        for (int it = 0; it < 4; ++it) {
            uint32_t off = base + sw128((uint32_t)(rr[it] * 128 + cc[it] * 2));
            uint32_t h0, h1, l0, l1;
            split4(pq[it], h0, h1, l0, l1);
            *(uint2*)(sm + 0 * TILE + off) = make_uint2(h0, h1);
            *(uint2*)(sm + 1 * TILE + off) = make_uint2(l0, l1);
            split4(pk[it], h0, h1, l0, l1);
            *(uint2*)(sm + 2 * TILE + off) = make_uint2(h0, h1);
            *(uint2*)(sm + 3 * TILE + off) = make_uint2(l0, l1);
        }
        __syncthreads();   // buf tiles ready (and, transitively, buf^1 MMAs done)

        // issue next stage's loads; consumed next iteration (overlaps MMA)
        if (s < 7) {
            const float* Qn = Qb + (size_t)(s + 1) * 64 * C;
            const float* Kn = Kb + (size_t)(s + 1) * 64 * C;
#pragma unroll
            for (int it = 0; it < 4; ++it) {
                pq[it] = *(const float4*)(Qn + (size_t)rr[it] * C + cc[it]);
                pk[it] = *(const float4*)(Kn + (size_t)rr[it] * C + cc[it]);
            }
        }

#pragma unroll
        for (int kst = 0; kst < 4; ++kst) {
            int r0 = kst * 16;
            uint32_t Ah[4], Al[4];
            uint32_t aoff = base + sw128((uint32_t)((r0 + rA) * 128 + cA * 2));
            LDSM4T(Ah, sb + 0 * TILE + aoff);
            LDSM4T(Al, sb + 1 * TILE + aoff);
#pragma unroll
            for (int j = 0; j < 2; ++j) {
                int np = nbase + j;
                uint32_t Bh[4], Bl[4];
                uint32_t boff =
                    base + sw128((uint32_t)((r0 + rB) * 128 + (np * 16 + cBo) * 2));
                LDSM4T(Bh, sb + 2 * TILE + boff);
                LDSM4T(Bl, sb + 3 * TILE + boff);
                float* d0 = d[2 * j];
                float* d1 = d[2 * j + 1];
                MMA(d0, Ah, Bh[0], Bh[1]); MMA(d1, Ah, Bh[2], Bh[3]);
                MMA(d0, Ah, Bl[0], Bl[1]); MMA(d1, Ah, Bl[2], Bl[3]);
                MMA(d0, Al, Bh[0], Bh[1]); MMA(d1, Al, Bh[2], Bh[3]);
            }
        }
        // no trailing barrier: next STS goes to the other buffer
    }

    float* pb = g_partial + ((size_t)b * CHUNKS + chunk) * (C * C);
    int mrow = qb + (lane >> 2);
    int mcol = 2 * (lane & 3);
#pragma unroll
    for (int j = 0; j < 2; ++j) {
        int np = nbase + j;
        *(float2*)(pb + mrow * C + np * 16 + mcol) =
            make_float2(d[2 * j][0], d[2 * j][1]);
        *(float2*)(pb + (mrow + 8) * C + np * 16 + mcol) =
            make_float2(d[2 * j][2], d[2 * j][3]);
        *(float2*)(pb + mrow * C + np * 16 + 8 + mcol) =
            make_float2(d[2 * j + 1][0], d[2 * j + 1][1]);
        *(float2*)(pb + (mrow + 8) * C + np * 16 + 8 + mcol) =
            make_float2(d[2 * j + 1][2], d[2 * j + 1][3]);
    }
}

// ---------------------------------------------------------------------------
// Kernel 2: reduce 32 chunk partials + softmax over k.
// ---------------------------------------------------------------------------
__global__ __launch_bounds__(256) void k2_softmax() {
    __shared__ float S[256];
    int b = blockIdx.x >> 4;
    int qg = blockIdx.x & 15;
    int t = threadIdx.x;
    int q = qg * 4 + (t >> 6);
    int k = t & 63;

    const float* p = g_partial + (size_t)b * CHUNKS * (C * C) + q * C + k;
    float acc = 0.f;
#pragma unroll 8
    for (int ch = 0; ch < CHUNKS; ++ch) acc += p[(size_t)ch * (C * C)];
    S[t] = acc;
    __syncthreads();

    int w = t >> 5, lane = t & 31;
    if (w < 4) {
        float e0 = S[w * 64 + lane];
        float e1 = S[w * 64 + 32 + lane];
        float m = fmaxf(e0, e1);
#pragma unroll
        for (int o = 16; o > 0; o >>= 1) m = fmaxf(m, __shfl_xor_sync(~0u, m, o));
        float x0 = expf(e0 - m), x1 = expf(e1 - m);
        float s = x0 + x1;
#pragma unroll
        for (int o = 16; o > 0; o >>= 1) s += __shfl_xor_sync(~0u, s, o);
        float inv = 1.f / s;
        float* a = g_attn + (size_t)b * (C * C) + (qg * 4 + w) * C;
        a[lane] = x0 * inv;
        a[lane + 32] = x1 * inv;
    }
}

// ---------------------------------------------------------------------------
// Kernel 3: out[b][r][q] = sum_k attn[b][q][k] * V[b][r][k]
// A = V (non-trans, double-buffered), B = attn (non-trans, staged once).
// Register prefetch of V; one barrier per stage.
// ---------------------------------------------------------------------------
__global__ void __launch_bounds__(256, 2)
k3_out(const float* __restrict__ V, float* __restrict__ O) {
    __shared__ __align__(1024) uint8_t sm[6 * TILE];   // Vh0 Vl0 Vh1 Vl1 Bh Bl
    uint32_t sb = smem_u32(sm);

    int t = threadIdx.x, lane = t & 31, w = t >> 5;
    int b = blockIdx.x >> 5;
    int rg = blockIdx.x & 31;
    size_t row0 = (size_t)b * HW + rg * 512;
    int rowg = (w & 3) * 16;
    int nbase = (w >> 2) * 2;

    int rr[4], cc[4];
#pragma unroll
    for (int it = 0; it < 4; ++it) {
        int idx = t + it * 256;
        rr[it] = idx >> 4;
        cc[it] = (idx & 15) * 4;
    }

    // stage attn once: B tile [q][k] hi/lo fp16
    const float* ab = g_attn + (size_t)b * (C * C);
#pragma unroll
    for (int it = 0; it < 4; ++it) {
        uint32_t off = sw128((uint32_t)(rr[it] * 128 + cc[it] * 2));
        uint32_t h0, h1, l0, l1;
        split4(*(const float4*)(ab + rr[it] * 64 + cc[it]), h0, h1, l0, l1);
        *(uint2*)(sm + 4 * TILE + off) = make_uint2(h0, h1);
        *(uint2*)(sm + 5 * TILE + off) = make_uint2(l0, l1);
    }

    const int li = lane & 7, mi = lane >> 3;
    const int rVA = rowg + ((mi & 1) << 3) + li;
    const int cVAo = (mi & 2) << 2;
    const int rBq = ((mi & 1) << 3) + li;
    const int cBo = (mi & 2) << 2;
    int mrow = rowg + (lane >> 2);
    int mcol = 2 * (lane & 3);

    float4 pv[4];
#pragma unroll
    for (int it = 0; it < 4; ++it)
        pv[it] = *(const float4*)(V + (row0 + rr[it]) * C + cc[it]);

    for (int s = 0; s < 8; ++s) {
        uint32_t base = (uint32_t)((s & 1) * 2 * TILE);
#pragma unroll
        for (int it = 0; it < 4; ++it) {
            uint32_t off = base + sw128((uint32_t)(rr[it] * 128 + cc[it] * 2));
            uint32_t h0, h1, l0, l1;
            split4(pv[it], h0, h1, l0, l1);
            *(uint2*)(sm + 0 * TILE + off) = make_uint2(h0, h1);
            *(uint2*)(sm + 1 * TILE + off) = make_uint2(l0, l1);
        }
        __syncthreads();   // V buf + (s=0) B ready

        if (s < 7) {
            const float* Vn = V + (row0 + (size_t)(s + 1) * 64) * C;
#pragma unroll
            for (int it = 0; it < 4; ++it)
                pv[it] = *(const float4*)(Vn + (size_t)rr[it] * C + cc[it]);
        }

        float d[4][4];
#pragma unroll
        for (int i = 0; i < 4; ++i)
#pragma unroll
            for (int j = 0; j < 4; ++j) d[i][j] = 0.f;

#pragma unroll
        for (int kst = 0; kst < 4; ++kst) {
            int k0 = kst * 16;
            uint32_t Ah[4], Al[4];
            uint32_t aoff = base + sw128((uint32_t)(rVA * 128 + (k0 + cVAo) * 2));
            LDSM4(Ah, sb + 0 * TILE + aoff);
            LDSM4(Al, sb + 1 * TILE + aoff);
#pragma unroll
            for (int j = 0; j < 2; ++j) {
                int np = nbase + j;
                uint32_t Bh[4], Bl[4];
                uint32_t boff =
                    sw128((uint32_t)((np * 16 + rBq) * 128 + (k0 + cBo) * 2));
                LDSM4(Bh, sb + 4 * TILE + boff);
                LDSM4(Bl, sb + 5 * TILE + boff);
                float* d0 = d[2 * j];
                float* d1 = d[2 * j + 1];
                MMA(d0, Ah, Bh[0], Bh[2]); MMA(d1, Ah, Bh[1], Bh[3]);
                MMA(d0, Ah, Bl[0], Bl[2]); MMA(d1, Ah, Bl[1], Bl[3]);
                MMA(d0, Al, Bh[0], Bh[2]); MMA(d1, Al, Bh[1], Bh[3]);
            }
        }

        float* Ob = O + (row0 + s * 64) * C;
#pragma unroll
        for (int j = 0; j < 2; ++j) {
            int np = nbase + j;
            *(float2*)(Ob + (size_t)mrow * C + np * 16 + mcol) =
                make_float2(d[2 * j][0], d[2 * j][1]);
            *(float2*)(Ob + (size_t)(mrow + 8) * C + np * 16 + mcol) =
                make_float2(d[2 * j][2], d[2 * j][3]);
            *(float2*)(Ob + (size_t)mrow * C + np * 16 + 8 + mcol) =
                make_float2(d[2 * j + 1][0], d[2 * j + 1][1]);
            *(float2*)(Ob + (size_t)(mrow + 8) * C + np * 16 + 8 + mcol) =
                make_float2(d[2 * j + 1][2], d[2 * j + 1][3]);
        }
        // no trailing barrier: next STS goes to the other V buffer
    }
}

// ---------------------------------------------------------------------------
extern "C" void kernel_launch(void* const* d_in, const int* in_sizes, int n_in,
                              void* d_out, int out_size) {
    const float* q = (const float*)d_in[0];
    const float* k = (const float*)d_in[1];
    const float* v = (const float*)d_in[2];
    float* out = (float*)d_out;

    k1_scores<<<BATCH * CHUNKS, 256>>>(q, k);
    k2_softmax<<<BATCH * 16, 256>>>();
    k3_out<<<BATCH * CHUNKS, 256>>>(v, out);
}